// round 12
// baseline (speedup 1.0000x reference)
#include <cuda_runtime.h>
#include <math.h>

#define TT 6
#define NN 50000
#define EE 800000
#define FF 32
#define HH 64
#define OUTC 16

#define TOTN (TT * NN)                 // 300000
#define SCAN_BLOCKS 1172               // ceil(TOTN/256)
#define AUX_PER_THREAD 5               // 256*5 = 1280 >= 1172
#define DEG_BPS   3125                 // EE/256
#define PLACE_BPS 3125
#define GATH_BPS  9375                 // TOTN*8/256
#define KK 96                          // FF + HH

// gate-GEMM (mma) config
#define NPB 128                        // nodes per block (8 warps x 16)
#define GATE_BLOCKS 391                // ceil(NN/128)
#define HSH_W 68                       // h shared stride (words): 4*g4+t4 -> all banks
#define BF_LANE_W 20                   // Bfrag per-lane stride (words): 80B -> conflict-free LDS.128
#define BF_KK_W (32 * BF_LANE_W)       // 640 words per kk row
// smem words: Hsh [128][68] fp32 | HRtf [128][68] tf32 | Bfrag [12][32][20]
#define SW_HSH   0
#define SW_HRTF  (128 * HSH_W)                  // 8704
#define SW_BFRAG (SW_HRTF + 128 * HSH_W)        // 17408
#define SMEM_GATES ((SW_BFRAG + 12 * BF_KK_W) * 4)   // 100352 bytes

typedef unsigned long long u64;

// ---------------- scratch (device globals; no allocation allowed) ----------
__device__ __align__(16) float g_aggx[(size_t)TT * NN * FF];  // A_hat@X, all steps
__device__ __align__(16) float g_h   [(size_t)NN * HH];
__device__ int   g_deg [TOTN];
__device__ int   g_roff[TOTN];
__device__ int   g_cur [TOTN];
__device__ int   g_bsum[SCAN_BLOCKS];
__device__ u64   g_csrp[(size_t)TT * EE];   // packed (src, norm) per edge
__device__ float g_dinv[TOTN];

// folded weights, k-major, tf32 bits: k<FF -> (W@L_top) fold; k>=FF -> L_bot
__device__ __align__(16) unsigned g_Wmma[3][KK][HH];
__device__ float g_bv[3][HH];

__device__ __forceinline__ float sigmoidf_(float x) {
    return 1.0f / (1.0f + __expf(-x));
}

__device__ __forceinline__ unsigned f2tf(float f) {
    unsigned r; asm("cvt.rna.tf32.f32 %0, %1;" : "=r"(r) : "f"(f)); return r;
}

__device__ __forceinline__ void mma8(float* d,
                                     unsigned a0, unsigned a1, unsigned a2, unsigned a3,
                                     unsigned b0, unsigned b1) {
    asm volatile("mma.sync.aligned.m16n8k8.row.col.f32.tf32.tf32.f32 "
        "{%0,%1,%2,%3}, {%4,%5,%6,%7}, {%8,%9}, {%0,%1,%2,%3};"
        : "+f"(d[0]), "+f"(d[1]), "+f"(d[2]), "+f"(d[3])
        : "r"(a0), "r"(a1), "r"(a2), "r"(a3), "r"(b0), "r"(b1));
}

// ---------------- prep / clears ---------------------------------------------

__global__ void k_clear_h() {
    unsigned idx = blockIdx.x * blockDim.x + threadIdx.x;
    if (idx < (unsigned)(NN * HH)) g_h[idx] = 0.0f;
}

__global__ void k_clear_int2() {
    unsigned i = blockIdx.x * blockDim.x + threadIdx.x;
    if (i < (unsigned)TOTN) { g_deg[i] = 0; g_cur[i] = 0; }
}

// one block per gate: build k-major tf32 weight panel + folded biases
__global__ void k_prep(const float* __restrict__ Wz, const float* __restrict__ bz,
                       const float* __restrict__ Wr, const float* __restrict__ br,
                       const float* __restrict__ Wh, const float* __restrict__ bh,
                       const float* __restrict__ Lz, const float* __restrict__ Lzb,
                       const float* __restrict__ Lr, const float* __restrict__ Lrb,
                       const float* __restrict__ Lh, const float* __restrict__ Lhb) {
    int g = blockIdx.x;
    int t = threadIdx.x;
    const float* W  = (g == 0) ? Wz  : (g == 1) ? Wr  : Wh;
    const float* b  = (g == 0) ? bz  : (g == 1) ? br  : bh;
    const float* L  = (g == 0) ? Lz  : (g == 1) ? Lr  : Lh;
    const float* Lb = (g == 0) ? Lzb : (g == 1) ? Lrb : Lhb;

    for (int e = t; e < KK * HH; e += 256) {
        int k = e >> 6, n = e & 63;
        float w;
        if (k < FF) {
            float s = 0.f;
            #pragma unroll 8
            for (int m = 0; m < HH; m++) s += __ldg(W + k * HH + m) * __ldg(L + m * HH + n);
            w = s;
        } else {
            w = __ldg(L + (k + 32) * HH + n);   // L_bot row (k-FF)+HH = k+32
        }
        g_Wmma[g][k][n] = f2tf(w);
    }
    if (t < HH) {
        float sb = __ldg(Lb + t);
        #pragma unroll 8
        for (int m = 0; m < HH; m++) sb += __ldg(b + m) * __ldg(L + m * HH + t);
        g_bv[g][t] = sb;
    }
}

// ---------------- degree ------------------------------------------------------

__global__ void k_deg_all(const int* __restrict__ ei) {
    int t = blockIdx.x / DEG_BPS;
    unsigned e = (blockIdx.x % DEG_BPS) * 256 + threadIdx.x;
    int d = __ldg(ei + (size_t)t * 2 * EE + EE + e);
    atomicAdd(&g_deg[t * NN + d], 1);
}

// ---------------- exclusive scan (+ dinv fused into pass 1) ------------------

__global__ void k_scan_block() {
    __shared__ int sh[256];
    int tid = threadIdx.x;
    int i = blockIdx.x * 256 + tid;
    int v = (i < TOTN) ? g_deg[i] : 0;
    if (i < TOTN) g_dinv[i] = rsqrtf((float)(v + 1));
    sh[tid] = v;
    __syncthreads();
    #pragma unroll
    for (int off = 1; off < 256; off <<= 1) {
        int tv = (tid >= off) ? sh[tid - off] : 0;
        __syncthreads();
        sh[tid] += tv;
        __syncthreads();
    }
    if (i < TOTN) g_roff[i] = sh[tid] - v;
    if (tid == 255) g_bsum[blockIdx.x] = sh[255];
}

__global__ void k_scan_aux() {
    __shared__ int part[256];
    int tid = threadIdx.x;
    int start = tid * AUX_PER_THREAD;
    int loc[AUX_PER_THREAD];
    int vv [AUX_PER_THREAD];
    int sum = 0;
    #pragma unroll
    for (int j = 0; j < AUX_PER_THREAD; j++) {
        int idx = start + j;
        int v = (idx < SCAN_BLOCKS) ? g_bsum[idx] : 0;
        vv[j] = v;
        sum += v;
        loc[j] = sum;
    }
    part[tid] = sum;
    __syncthreads();
    #pragma unroll
    for (int off = 1; off < 256; off <<= 1) {
        int tv = (tid >= off) ? part[tid - off] : 0;
        __syncthreads();
        part[tid] += tv;
        __syncthreads();
    }
    int prev = (tid > 0) ? part[tid - 1] : 0;
    #pragma unroll
    for (int j = 0; j < AUX_PER_THREAD; j++) {
        int idx = start + j;
        if (idx < SCAN_BLOCKS) g_bsum[idx] = prev + loc[j] - vv[j];
    }
}

__global__ void k_scan_add() {
    int i = blockIdx.x * 256 + threadIdx.x;
    if (i < TOTN) g_roff[i] += g_bsum[blockIdx.x];
}

// ---------------- CSR placement (packed src + norm) -------------------------

__global__ void k_place(const int* __restrict__ ei) {
    int t = blockIdx.x / PLACE_BPS;
    unsigned e = (blockIdx.x % PLACE_BPS) * 256 + threadIdx.x;
    const int* base = ei + (size_t)t * 2 * EE;
    int s = __ldg(base + e);
    int d = __ldg(base + EE + e);
    int i = t * NN + d;
    int pos = g_roff[i] + atomicAdd(&g_cur[i], 1);
    float w = __ldg(&g_dinv[t * NN + s]) * __ldg(&g_dinv[i]);
    g_csrp[pos] = (u64)(unsigned)s | ((u64)__float_as_uint(w) << 32);
}

// ---------------- pull-mode gather (R10 version, unchanged) -----------------

__global__ void k_gather(const float* __restrict__ xs) {
    unsigned idx = blockIdx.x * 256 + threadIdx.x;   // < TOTN*8
    unsigned nf = idx >> 3;          // flat (t,node)
    unsigned c  = idx & 7u;
    int t = nf / NN;
    int node = nf - t * NN;
    const float* x = xs + (size_t)t * NN * FF;

    float dd = g_dinv[nf];
    float4 acc = __ldg(reinterpret_cast<const float4*>(x + (size_t)node * FF) + c);
    float d2 = dd * dd;
    acc.x *= d2; acc.y *= d2; acc.z *= d2; acc.w *= d2;

    int beg = g_roff[nf];
    int end = beg + g_deg[nf];
    for (int p = beg; p < end; p++) {
        u64 rec = __ldg(g_csrp + p);
        int s = (int)(unsigned)(rec & 0xffffffffULL);
        float ns = __uint_as_float((unsigned)(rec >> 32));
        float4 v = __ldg(reinterpret_cast<const float4*>(x + (size_t)s * FF) + c);
        acc.x = fmaf(v.x, ns, acc.x);
        acc.y = fmaf(v.y, ns, acc.y);
        acc.z = fmaf(v.z, ns, acc.z);
        acc.w = fmaf(v.w, ns, acc.w);
    }
    reinterpret_cast<float4*>(g_aggx + (size_t)nf * FF)[c] = acc;
}

// ---------------- GRU gates on tensor cores (mma.sync tf32, v2) -------------
// Block: 256 thr = 8 warps, 128 nodes. Warp: 16 nodes.
// v2: h staged in shared once (coalesced); B panel staged fragment-major so
// each k-step needs 4x LDS.128 instead of 16 scalar LDS.

__global__ void __launch_bounds__(256) k_gates_mma(int t) {
    extern __shared__ float smem_f[];
    float*    Hsh   = smem_f + SW_HSH;               // [128][HSH_W] fp32
    unsigned* HRtf  = (unsigned*)smem_f + SW_HRTF;   // [128][HSH_W] tf32
    unsigned* Bfrag = (unsigned*)smem_f + SW_BFRAG;  // [12][32][BF_LANE_W]

    int tid = threadIdx.x;
    int lane = tid & 31;
    int g4 = lane >> 2, t4 = lane & 3;
    int warp = tid >> 5;
    int wnb = warp * 16;                   // warp's block-local node base

    const float* aggx_t = g_aggx + (size_t)t * NN * FF;
    int block_base = blockIdx.x * NPB;

    int r0 = block_base + wnb + g4;
    int r1 = r0 + 8;
    bool v0 = r0 < NN, v1 = r1 < NN;
    int l0 = wnb + g4, l1 = l0 + 8;        // block-local rows

    // stage h (128 nodes x 64) into Hsh, coalesced float4
    #pragma unroll
    for (int r = 0; r < 8; r++) {
        int idx = r * 256 + tid;           // 0..2047 float4s
        int n = idx >> 4, k4 = idx & 15;
        int node = block_base + n;
        float4 v = make_float4(0.f, 0.f, 0.f, 0.f);
        if (node < NN) v = __ldg(reinterpret_cast<const float4*>(g_h + (size_t)node * HH) + k4);
        *reinterpret_cast<float4*>(&Hsh[n * HSH_W + k4 * 4]) = v;
    }

    // resident aggx A-fragments (k-steps 0..3)
    unsigned Aa[4][4];
    #pragma unroll
    for (int kk = 0; kk < 4; kk++) {
        int c0 = kk * 8 + t4, c1 = c0 + 4;
        Aa[kk][0] = f2tf(v0 ? __ldg(aggx_t + (size_t)r0 * FF + c0) : 0.f);
        Aa[kk][1] = f2tf(v1 ? __ldg(aggx_t + (size_t)r1 * FF + c0) : 0.f);
        Aa[kk][2] = f2tf(v0 ? __ldg(aggx_t + (size_t)r0 * FF + c1) : 0.f);
        Aa[kk][3] = f2tf(v1 ? __ldg(aggx_t + (size_t)r1 * FF + c1) : 0.f);
    }

    float Z[8][4];
    float acc[8][4];

    for (int gate = 0; gate < 3; gate++) {
        __syncthreads();                   // Hsh ready (gate 0) / Bfrag reuse
        // stage this gate's weight panel in FRAGMENT-MAJOR layout
        const unsigned* Wg = &g_Wmma[gate][0][0];
        for (int i = tid; i < 12 * 32 * 8; i += 256) {
            int nt = i & 7;
            int ln = (i >> 3) & 31;
            int kk = i >> 8;
            int t4s = ln & 3, g4s = ln >> 2;
            unsigned b0 = Wg[(kk * 8 + t4s) * HH + nt * 8 + g4s];
            unsigned b1 = Wg[(kk * 8 + t4s + 4) * HH + nt * 8 + g4s];
            *reinterpret_cast<uint2*>(&Bfrag[kk * BF_KK_W + ln * BF_LANE_W + nt * 2]) =
                make_uint2(b0, b1);
        }
        __syncthreads();

        #pragma unroll
        for (int nt = 0; nt < 8; nt++)
            #pragma unroll
            for (int q = 0; q < 4; q++) acc[nt][q] = 0.f;

        #pragma unroll
        for (int kk = 0; kk < 12; kk++) {
            unsigned a0, a1, a2, a3;
            if (kk < 4) {
                a0 = Aa[kk][0]; a1 = Aa[kk][1]; a2 = Aa[kk][2]; a3 = Aa[kk][3];
            } else {
                int c0 = (kk - 4) * 8 + t4, c1 = c0 + 4;
                if (gate < 2) {
                    a0 = f2tf(Hsh[l0 * HSH_W + c0]);
                    a1 = f2tf(Hsh[l1 * HSH_W + c0]);
                    a2 = f2tf(Hsh[l0 * HSH_W + c1]);
                    a3 = f2tf(Hsh[l1 * HSH_W + c1]);
                } else {
                    a0 = HRtf[l0 * HSH_W + c0];
                    a1 = HRtf[l1 * HSH_W + c0];
                    a2 = HRtf[l0 * HSH_W + c1];
                    a3 = HRtf[l1 * HSH_W + c1];
                }
            }
            const uint4* bp = reinterpret_cast<const uint4*>(
                &Bfrag[kk * BF_KK_W + lane * BF_LANE_W]);
            uint4 q0 = bp[0], q1 = bp[1], q2 = bp[2], q3 = bp[3];
            unsigned w[16] = {q0.x, q0.y, q0.z, q0.w, q1.x, q1.y, q1.z, q1.w,
                              q2.x, q2.y, q2.z, q2.w, q3.x, q3.y, q3.z, q3.w};
            #pragma unroll
            for (int nt = 0; nt < 8; nt++)
                mma8(acc[nt], a0, a1, a2, a3, w[nt * 2], w[nt * 2 + 1]);
        }

        if (gate == 0) {
            #pragma unroll
            for (int nt = 0; nt < 8; nt++) {
                int col = nt * 8 + 2 * t4;
                float ba = __ldg(&g_bv[0][col]), bb = __ldg(&g_bv[0][col + 1]);
                Z[nt][0] = sigmoidf_(acc[nt][0] + ba);
                Z[nt][1] = sigmoidf_(acc[nt][1] + bb);
                Z[nt][2] = sigmoidf_(acc[nt][2] + ba);
                Z[nt][3] = sigmoidf_(acc[nt][3] + bb);
            }
        } else if (gate == 1) {
            #pragma unroll
            for (int nt = 0; nt < 8; nt++) {
                int col = nt * 8 + 2 * t4;
                float ba = __ldg(&g_bv[1][col]), bb = __ldg(&g_bv[1][col + 1]);
                float h00 = Hsh[l0 * HSH_W + col];
                float h01 = Hsh[l0 * HSH_W + col + 1];
                float h10 = Hsh[l1 * HSH_W + col];
                float h11 = Hsh[l1 * HSH_W + col + 1];
                HRtf[l0 * HSH_W + col]     = f2tf(h00 * sigmoidf_(acc[nt][0] + ba));
                HRtf[l0 * HSH_W + col + 1] = f2tf(h01 * sigmoidf_(acc[nt][1] + bb));
                HRtf[l1 * HSH_W + col]     = f2tf(h10 * sigmoidf_(acc[nt][2] + ba));
                HRtf[l1 * HSH_W + col + 1] = f2tf(h11 * sigmoidf_(acc[nt][3] + bb));
            }
            __syncwarp();                  // HRtf is warp-private
        } else {
            #pragma unroll
            for (int nt = 0; nt < 8; nt++) {
                int col = nt * 8 + 2 * t4;
                float ba = __ldg(&g_bv[2][col]), bb = __ldg(&g_bv[2][col + 1]);
                float Ht0 = tanhf(acc[nt][0] + ba);
                float Ht1 = tanhf(acc[nt][1] + bb);
                float Ht2 = tanhf(acc[nt][2] + ba);
                float Ht3 = tanhf(acc[nt][3] + bb);
                if (v0) {
                    float h00 = Hsh[l0 * HSH_W + col];
                    float h01 = Hsh[l0 * HSH_W + col + 1];
                    float o0 = Z[nt][0] * h00 + (1.f - Z[nt][0]) * Ht0;
                    float o1 = Z[nt][1] * h01 + (1.f - Z[nt][1]) * Ht1;
                    *reinterpret_cast<float2*>(g_h + (size_t)r0 * HH + col) = make_float2(o0, o1);
                }
                if (v1) {
                    float h10 = Hsh[l1 * HSH_W + col];
                    float h11 = Hsh[l1 * HSH_W + col + 1];
                    float o2 = Z[nt][2] * h10 + (1.f - Z[nt][2]) * Ht2;
                    float o3 = Z[nt][3] * h11 + (1.f - Z[nt][3]) * Ht3;
                    *reinterpret_cast<float2*>(g_h + (size_t)r1 * HH + col) = make_float2(o2, o3);
                }
            }
        }
    }
}

__global__ void k_out(const float* __restrict__ oW, const float* __restrict__ ob,
                      float* __restrict__ out) {
    unsigned idx = blockIdx.x * blockDim.x + threadIdx.x;
    if (idx >= (unsigned)(NN * OUTC)) return;
    int i = idx >> 4, j = idx & 15;
    const float* hr = g_h + (size_t)i * HH;
    float acc = __ldg(ob + j);
    #pragma unroll
    for (int k = 0; k < HH; k++) acc += hr[k] * __ldg(oW + k * OUTC + j);
    out[idx] = acc;
}

// ---------------- launch ----------------------------------------------------
extern "C" void kernel_launch(void* const* d_in, const int* in_sizes, int n_in,
                              void* d_out, int out_size) {
    const float* xs  = (const float*)d_in[0];
    const int*   ei  = (const int*)  d_in[1];
    const float* Wz  = (const float*)d_in[2];
    const float* bz  = (const float*)d_in[3];
    const float* Wr  = (const float*)d_in[4];
    const float* br  = (const float*)d_in[5];
    const float* Wh  = (const float*)d_in[6];
    const float* bh  = (const float*)d_in[7];
    const float* Lz  = (const float*)d_in[8];
    const float* Lzb = (const float*)d_in[9];
    const float* Lr  = (const float*)d_in[10];
    const float* Lrb = (const float*)d_in[11];
    const float* Lh  = (const float*)d_in[12];
    const float* Lhb = (const float*)d_in[13];
    const float* oW  = (const float*)d_in[14];
    const float* ob  = (const float*)d_in[15];
    float* out = (float*)d_out;

    cudaFuncSetAttribute(k_gates_mma, cudaFuncAttributeMaxDynamicSharedMemorySize,
                         SMEM_GATES);

    k_prep<<<3, 256>>>(Wz, bz, Wr, br, Wh, bh, Lz, Lzb, Lr, Lrb, Lh, Lhb);
    k_clear_h<<<(NN * HH + 255) / 256, 256>>>();
    k_clear_int2<<<SCAN_BLOCKS, 256>>>();

    k_deg_all<<<TT * DEG_BPS, 256>>>(ei);
    k_scan_block<<<SCAN_BLOCKS, 256>>>();
    k_scan_aux<<<1, 256>>>();
    k_scan_add<<<SCAN_BLOCKS, 256>>>();
    k_place<<<TT * PLACE_BPS, 256>>>(ei);
    k_gather<<<GATH_BPS, 256>>>(xs);

    for (int t = 0; t < TT; t++)
        k_gates_mma<<<GATE_BLOCKS, 256, SMEM_GATES>>>(t);

    k_out<<<(NN * OUTC + 255) / 256, 256>>>(oW, ob, out);
}